// round 12
// baseline (speedup 1.0000x reference)
#include <cuda_runtime.h>
#include <math.h>

#define S_LEN 4096
#define D_MODEL 1024
#define NH 16
#define DHD 64

// ---- scratch (static device globals: allocation-free contract) ----
__device__ float g_h[S_LEN * D_MODEL];
__device__ float g_q[S_LEN * D_MODEL];
__device__ float g_k[S_LEN * D_MODEL];
__device__ float g_v[S_LEN * D_MODEL];
__device__ float g_att[S_LEN * D_MODEL];
__device__ float g_proj[S_LEN * D_MODEL];

// ---------------------------------------------------------------------------
// h = x + positional_encoding
// ---------------------------------------------------------------------------
__global__ void add_pe_kernel(const float* __restrict__ x, float* __restrict__ h) {
    int srow = blockIdx.x;
    int tid = threadIdx.x;
#pragma unroll
    for (int n = 0; n < 4; n++) {
        int d = tid + n * 256;
        float arg = (float)(d & ~1) * (-9.2103403719761836f / 1024.0f);  // -ln(10000)/D
        float dv = expf(arg);
        float a = (float)srow * dv;
        float pe = (d & 1) ? cosf(a) : sinf(a);
        int idx = srow * D_MODEL + d;
        h[idx] = x[idx] + pe;
    }
}

// ---------------------------------------------------------------------------
// tf32 helpers
// ---------------------------------------------------------------------------
__device__ __forceinline__ unsigned f2tf32(float x) {
    unsigned r;
    asm("cvt.rna.tf32.f32 %0, %1;" : "=r"(r) : "f"(x));
    return r;
}

__device__ __forceinline__ void mma_tf32(
    float& c0, float& c1, float& c2, float& c3,
    unsigned a0, unsigned a1, unsigned a2, unsigned a3,
    unsigned b0, unsigned b1) {
    asm("mma.sync.aligned.m16n8k8.row.col.f32.tf32.tf32.f32 "
        "{%0,%1,%2,%3}, {%4,%5,%6,%7}, {%8,%9}, {%0,%1,%2,%3};"
        : "+f"(c0), "+f"(c1), "+f"(c2), "+f"(c3)
        : "r"(a0), "r"(a1), "r"(a2), "r"(a3), "r"(b0), "r"(b1));
}

// ---------------------------------------------------------------------------
// 128x128x16 tf32 tensor-core GEMM body (validated R6), double-buffered.
// ---------------------------------------------------------------------------
#define KT 16
#define PITCH 136

__device__ __forceinline__ void sgemm_body(
    const float* __restrict__ A, const float* __restrict__ B,
    const float* __restrict__ bias, float* __restrict__ C,
    int M, int N, int K, int m0, int n0) {
    __shared__ unsigned As[2][KT][PITCH];
    __shared__ unsigned Bs[2][KT][PITCH];

    int tid = threadIdx.x;
    int wid = tid >> 5;
    int lane = tid & 31;
    int gid = lane >> 2;       // 0..7
    int tig = lane & 3;        // 0..3
    int wm = (wid & 3) * 32;   // warp row offset in tile
    int wn = (wid >> 2) * 64;  // warp col offset in tile

    int arow = tid >> 1;
    int acol = (tid & 1) * 4;
    int brow = tid >> 5;
    int bcol = (tid & 31) * 4;

    const float* Aptr = &A[(size_t)(m0 + arow) * K + acol];
    const float* Bptr = &B[(size_t)brow * N + n0 + bcol];

    float acc[2][8][4];
#pragma unroll
    for (int mt = 0; mt < 2; mt++)
#pragma unroll
        for (int nt = 0; nt < 8; nt++)
#pragma unroll
            for (int r = 0; r < 4; r++) acc[mt][nt][r] = 0.f;

    float4 a0p = *(const float4*)Aptr;
    float4 a1p = *(const float4*)(Aptr + 8);
    float4 b0p = *(const float4*)Bptr;
    float4 b1p = *(const float4*)(Bptr + (size_t)8 * N);
#pragma unroll
    for (int i = 0; i < 4; i++) {
        As[0][acol + i][arow]     = f2tf32(((const float*)&a0p)[i]);
        As[0][acol + 8 + i][arow] = f2tf32(((const float*)&a1p)[i]);
        Bs[0][brow][bcol + i]     = f2tf32(((const float*)&b0p)[i]);
        Bs[0][brow + 8][bcol + i] = f2tf32(((const float*)&b1p)[i]);
    }
    __syncthreads();

    int buf = 0;
    for (int k0 = 0; k0 < K; k0 += KT) {
        if (k0 + KT < K) {
            a0p = *(const float4*)(Aptr + k0 + KT);
            a1p = *(const float4*)(Aptr + k0 + KT + 8);
            b0p = *(const float4*)(Bptr + (size_t)(k0 + KT) * N);
            b1p = *(const float4*)(Bptr + (size_t)(k0 + KT + 8) * N);
        }

#pragma unroll
        for (int ks = 0; ks < KT; ks += 8) {
            unsigned af[2][4], bf[8][2];
#pragma unroll
            for (int mt = 0; mt < 2; mt++) {
                int r = wm + mt * 16 + gid;
                af[mt][0] = As[buf][ks + tig][r];
                af[mt][1] = As[buf][ks + tig][r + 8];
                af[mt][2] = As[buf][ks + tig + 4][r];
                af[mt][3] = As[buf][ks + tig + 4][r + 8];
            }
#pragma unroll
            for (int nt = 0; nt < 8; nt++) {
                int c = wn + nt * 8 + gid;
                bf[nt][0] = Bs[buf][ks + tig][c];
                bf[nt][1] = Bs[buf][ks + tig + 4][c];
            }
#pragma unroll
            for (int mt = 0; mt < 2; mt++)
#pragma unroll
                for (int nt = 0; nt < 8; nt++)
                    mma_tf32(acc[mt][nt][0], acc[mt][nt][1],
                             acc[mt][nt][2], acc[mt][nt][3],
                             af[mt][0], af[mt][1], af[mt][2], af[mt][3],
                             bf[nt][0], bf[nt][1]);
        }

        if (k0 + KT < K) {
            int nb = buf ^ 1;
#pragma unroll
            for (int i = 0; i < 4; i++) {
                As[nb][acol + i][arow]     = f2tf32(((const float*)&a0p)[i]);
                As[nb][acol + 8 + i][arow] = f2tf32(((const float*)&a1p)[i]);
                Bs[nb][brow][bcol + i]     = f2tf32(((const float*)&b0p)[i]);
                Bs[nb][brow + 8][bcol + i] = f2tf32(((const float*)&b1p)[i]);
            }
            __syncthreads();
            buf = nb;
        }
    }

#pragma unroll
    for (int mt = 0; mt < 2; mt++) {
#pragma unroll
        for (int nt = 0; nt < 8; nt++) {
            int row = m0 + wm + mt * 16 + gid;
            int col = n0 + wn + nt * 8 + tig * 2;
            float2 r0, r1;
            r0.x = acc[mt][nt][0] + bias[col];
            r0.y = acc[mt][nt][1] + bias[col + 1];
            r1.x = acc[mt][nt][2] + bias[col];
            r1.y = acc[mt][nt][3] + bias[col + 1];
            *(float2*)&C[(size_t)row * N + col]       = r0;
            *(float2*)&C[(size_t)(row + 8) * N + col] = r1;
        }
    }
}

__global__ __launch_bounds__(256, 2) void sgemm_bias_kernel(
    const float* __restrict__ A, const float* __restrict__ B,
    const float* __restrict__ bias, float* __restrict__ C,
    int M, int N, int K) {
    sgemm_body(A, B, bias, C, M, N, K, blockIdx.y * 128, blockIdx.x * 128);
}

__global__ __launch_bounds__(256, 2) void sgemm_qkv_kernel(
    const float* __restrict__ A,
    const float* __restrict__ Wq, const float* __restrict__ bq, float* __restrict__ q,
    const float* __restrict__ Wk, const float* __restrict__ bk, float* __restrict__ k,
    const float* __restrict__ Wv, const float* __restrict__ bv, float* __restrict__ v) {
    const float* B;
    const float* bias;
    float* C;
    if (blockIdx.z == 0)      { B = Wq; bias = bq; C = q; }
    else if (blockIdx.z == 1) { B = Wk; bias = bk; C = k; }
    else                      { B = Wv; bias = bv; C = v; }
    sgemm_body(A, B, bias, C, S_LEN, D_MODEL, D_MODEL,
               blockIdx.y * 128, blockIdx.x * 128);
}

// ---------------------------------------------------------------------------
// Flash attention with tf32 tensor cores (R8 validated layout).
// R9 delta (fourth submission attempt): (1) K/V next-tile register prefetch;
// (2) Vs pitch 72 -> PV B-loads bank-conflict-free.
// ---------------------------------------------------------------------------
#define FP 68
#define VP 72
#define FLASH_SMEM ((2 * 64 * FP + 64 * VP) * 4)

__global__ __launch_bounds__(128, 3) void flash_tc_kernel(
    const float* __restrict__ q, const float* __restrict__ k,
    const float* __restrict__ v, float* __restrict__ o_out) {
    extern __shared__ unsigned fsm[];
    unsigned* Ks = fsm;               // [key][dh]   64 x FP
    unsigned* Vs = fsm + 64 * FP;     // [key][dh]   64 x VP
    unsigned* Ps = Vs + 64 * VP;      // [qrow][key] 64 x FP

    int head = blockIdx.y;
    int qt = blockIdx.x;
    int tid = threadIdx.x;
    int wid = tid >> 5;
    int lane = tid & 31;
    int gid = lane >> 2;  // 0..7
    int tig = lane & 3;   // 0..3

    // per-thread K/V load coordinates
    int lkey[8], ld4[8];
#pragma unroll
    for (int n = 0; n < 8; n++) {
        int f4 = n * 128 + tid;
        lkey[n] = f4 >> 4;
        ld4[n] = (f4 & 15) * 4;
    }

    // preload Q A-fragments (x 1/8 scale), constant over all kt tiles
    unsigned aq[8][4];
    {
        const float* qb = q + (size_t)(qt * 64 + wid * 16) * D_MODEL + head * DHD;
#pragma unroll
        for (int ks = 0; ks < 8; ks++) {
            int c0 = ks * 8 + tig;
            aq[ks][0] = f2tf32(0.125f * qb[(size_t)gid * D_MODEL + c0]);
            aq[ks][1] = f2tf32(0.125f * qb[(size_t)(gid + 8) * D_MODEL + c0]);
            aq[ks][2] = f2tf32(0.125f * qb[(size_t)gid * D_MODEL + c0 + 4]);
            aq[ks][3] = f2tf32(0.125f * qb[(size_t)(gid + 8) * D_MODEL + c0 + 4]);
        }
    }

    float m0 = -INFINITY, m1 = -INFINITY, l0 = 0.f, l1 = 0.f;
    float o[8][4];
#pragma unroll
    for (int nt = 0; nt < 8; nt++)
#pragma unroll
        for (int r = 0; r < 4; r++) o[nt][r] = 0.f;

    int pr0 = wid * 16 + gid;       // this thread's P/O rows (warp-local tile)
    int pr1 = pr0 + 8;

    const float* kbase = k + head * DHD;
    const float* vbase = v + head * DHD;

    // prefetch tile 0 into registers
    float4 kreg[8], vreg[8];
#pragma unroll
    for (int n = 0; n < 8; n++) {
        kreg[n] = *(const float4*)&kbase[(size_t)lkey[n] * D_MODEL + ld4[n]];
        vreg[n] = *(const float4*)&vbase[(size_t)lkey[n] * D_MODEL + ld4[n]];
    }

    for (int kt = 0; kt < S_LEN / 64; kt++) {
        // ---- commit prefetched regs -> smem (tf32) ----
#pragma unroll
        for (int n = 0; n < 8; n++) {
            uint4 ku = {f2tf32(kreg[n].x), f2tf32(kreg[n].y),
                        f2tf32(kreg[n].z), f2tf32(kreg[n].w)};
            uint4 vu = {f2tf32(vreg[n].x), f2tf32(vreg[n].y),
                        f2tf32(vreg[n].z), f2tf32(vreg[n].w)};
            *(uint4*)&Ks[lkey[n] * FP + ld4[n]] = ku;
            *(uint4*)&Vs[lkey[n] * VP + ld4[n]] = vu;
        }
        __syncthreads();

        // ---- prefetch next tile while computing this one ----
        if (kt + 1 < S_LEN / 64) {
            const float* kb = kbase + (size_t)(kt + 1) * 64 * D_MODEL;
            const float* vb = vbase + (size_t)(kt + 1) * 64 * D_MODEL;
#pragma unroll
            for (int n = 0; n < 8; n++) {
                kreg[n] = *(const float4*)&kb[(size_t)lkey[n] * D_MODEL + ld4[n]];
                vreg[n] = *(const float4*)&vb[(size_t)lkey[n] * D_MODEL + ld4[n]];
            }
        }

        // ---- S = (Q/8) K^T  (pre-scaled) ----
        float s[8][4];
#pragma unroll
        for (int nt = 0; nt < 8; nt++)
#pragma unroll
            for (int r = 0; r < 4; r++) s[nt][r] = 0.f;

#pragma unroll
        for (int ks = 0; ks < 8; ks++) {
#pragma unroll
            for (int nt = 0; nt < 8; nt++) {
                int key = nt * 8 + gid;
                unsigned b0 = Ks[key * FP + ks * 8 + tig];
                unsigned b1 = Ks[key * FP + ks * 8 + tig + 4];
                mma_tf32(s[nt][0], s[nt][1], s[nt][2], s[nt][3],
                         aq[ks][0], aq[ks][1], aq[ks][2], aq[ks][3], b0, b1);
            }
        }

        // ---- online softmax (rows pr0=gid, pr1=gid+8 within warp tile) ----
        float mx0 = -INFINITY, mx1 = -INFINITY;
#pragma unroll
        for (int nt = 0; nt < 8; nt++) {
            mx0 = fmaxf(mx0, fmaxf(s[nt][0], s[nt][1]));
            mx1 = fmaxf(mx1, fmaxf(s[nt][2], s[nt][3]));
        }
        mx0 = fmaxf(mx0, __shfl_xor_sync(0xffffffffu, mx0, 1));
        mx0 = fmaxf(mx0, __shfl_xor_sync(0xffffffffu, mx0, 2));
        mx1 = fmaxf(mx1, __shfl_xor_sync(0xffffffffu, mx1, 1));
        mx1 = fmaxf(mx1, __shfl_xor_sync(0xffffffffu, mx1, 2));

        float mn0 = fmaxf(m0, mx0);
        float mn1 = fmaxf(m1, mx1);
        float c0 = __expf(m0 - mn0);
        float c1 = __expf(m1 - mn1);
        float rs0 = 0.f, rs1 = 0.f;
#pragma unroll
        for (int nt = 0; nt < 8; nt++) {
            s[nt][0] = __expf(s[nt][0] - mn0);
            s[nt][1] = __expf(s[nt][1] - mn0);
            s[nt][2] = __expf(s[nt][2] - mn1);
            s[nt][3] = __expf(s[nt][3] - mn1);
            rs0 += s[nt][0] + s[nt][1];
            rs1 += s[nt][2] + s[nt][3];
        }
        rs0 += __shfl_xor_sync(0xffffffffu, rs0, 1);
        rs0 += __shfl_xor_sync(0xffffffffu, rs0, 2);
        rs1 += __shfl_xor_sync(0xffffffffu, rs1, 1);
        rs1 += __shfl_xor_sync(0xffffffffu, rs1, 2);
        l0 = l0 * c0 + rs0;
        l1 = l1 * c1 + rs1;
        m0 = mn0;
        m1 = mn1;
#pragma unroll
        for (int nt = 0; nt < 8; nt++) {
            o[nt][0] *= c0;
            o[nt][1] *= c0;
            o[nt][2] *= c1;
            o[nt][3] *= c1;
        }

        // ---- P -> smem (tf32), warp-private rows ----
#pragma unroll
        for (int nt = 0; nt < 8; nt++) {
            int col = nt * 8 + tig * 2;
            uint2 p0 = {f2tf32(s[nt][0]), f2tf32(s[nt][1])};
            uint2 p1 = {f2tf32(s[nt][2]), f2tf32(s[nt][3])};
            *(uint2*)&Ps[pr0 * FP + col] = p0;
            *(uint2*)&Ps[pr1 * FP + col] = p1;
        }
        __syncwarp();

        // ---- O += P V ----
#pragma unroll
        for (int ks = 0; ks < 8; ks++) {
            unsigned ap0 = Ps[pr0 * FP + ks * 8 + tig];
            unsigned ap1 = Ps[pr1 * FP + ks * 8 + tig];
            unsigned ap2 = Ps[pr0 * FP + ks * 8 + tig + 4];
            unsigned ap3 = Ps[pr1 * FP + ks * 8 + tig + 4];
#pragma unroll
            for (int nt = 0; nt < 8; nt++) {
                unsigned b0 = Vs[(ks * 8 + tig) * VP + nt * 8 + gid];
                unsigned b1 = Vs[(ks * 8 + tig + 4) * VP + nt * 8 + gid];
                mma_tf32(o[nt][0], o[nt][1], o[nt][2], o[nt][3],
                         ap0, ap1, ap2, ap3, b0, b1);
            }
        }
        __syncthreads();  // Ks/Vs rewritten next tile
    }

    // ---- epilogue: O / l ----
    float inv0 = 1.0f / l0;
    float inv1 = 1.0f / l1;
    float* ob = o_out + (size_t)(qt * 64 + wid * 16) * D_MODEL + head * DHD;
#pragma unroll
    for (int nt = 0; nt < 8; nt++) {
        int col = nt * 8 + tig * 2;
        float2 r0 = {o[nt][0] * inv0, o[nt][1] * inv0};
        float2 r1 = {o[nt][2] * inv1, o[nt][3] * inv1};
        *(float2*)&ob[(size_t)gid * D_MODEL + col]       = r0;
        *(float2*)&ob[(size_t)(gid + 8) * D_MODEL + col] = r1;
    }
}

// ---------------------------------------------------------------------------
// y = LN(h + proj) * gamma + beta   (one block per row)
// ---------------------------------------------------------------------------
__global__ __launch_bounds__(256) void ln_kernel(
    const float* __restrict__ h, const float* __restrict__ p,
    const float* __restrict__ gamma, const float* __restrict__ beta,
    float* __restrict__ out) {
    int row = blockIdx.x;
    int tid = threadIdx.x;
    float v[4];
    float s = 0.f, s2 = 0.f;
#pragma unroll
    for (int n = 0; n < 4; n++) {
        int c = tid + n * 256;
        float val = h[(size_t)row * D_MODEL + c] + p[(size_t)row * D_MODEL + c];
        v[n] = val;
        s += val;
        s2 += val * val;
    }
#pragma unroll
    for (int off = 16; off >= 1; off >>= 1) {
        s += __shfl_xor_sync(0xffffffffu, s, off);
        s2 += __shfl_xor_sync(0xffffffffu, s2, off);
    }
    __shared__ float sb[8], sb2[8];
    int w = tid >> 5, lane = tid & 31;
    if (lane == 0) { sb[w] = s; sb2[w] = s2; }
    __syncthreads();
    if (tid == 0) {
        float a = 0.f, b = 0.f;
        for (int i = 0; i < 8; i++) { a += sb[i]; b += sb2[i]; }
        sb[0] = a; sb2[0] = b;
    }
    __syncthreads();
    float mean = sb[0] * (1.0f / 1024.0f);
    float var = sb2[0] * (1.0f / 1024.0f) - mean * mean;
    float inv = rsqrtf(var + 1e-5f);
#pragma unroll
    for (int n = 0; n < 4; n++) {
        int c = tid + n * 256;
        out[(size_t)row * D_MODEL + c] = (v[n] - mean) * inv * gamma[c] + beta[c];
    }
}

// ---------------------------------------------------------------------------
extern "C" void kernel_launch(void* const* d_in, const int* in_sizes, int n_in,
                              void* d_out, int out_size) {
    const float* x  = (const float*)d_in[0];
    const float* Wq = (const float*)d_in[1];
    const float* bq = (const float*)d_in[2];
    const float* Wk = (const float*)d_in[3];
    const float* bk = (const float*)d_in[4];
    const float* Wv = (const float*)d_in[5];
    const float* bv = (const float*)d_in[6];
    const float* Wo = (const float*)d_in[7];
    const float* bo = (const float*)d_in[8];
    const float* gamma = (const float*)d_in[9];
    const float* beta  = (const float*)d_in[10];
    float* out = (float*)d_out;

    void *ph, *pq, *pk, *pv, *pa, *pp;
    cudaGetSymbolAddress(&ph, g_h);
    cudaGetSymbolAddress(&pq, g_q);
    cudaGetSymbolAddress(&pk, g_k);
    cudaGetSymbolAddress(&pv, g_v);
    cudaGetSymbolAddress(&pa, g_att);
    cudaGetSymbolAddress(&pp, g_proj);

    add_pe_kernel<<<S_LEN, 256>>>(x, (float*)ph);

    dim3 qkvgrid(D_MODEL / 128, S_LEN / 128, 3);
    sgemm_qkv_kernel<<<qkvgrid, 256>>>((const float*)ph,
                                       Wq, bq, (float*)pq,
                                       Wk, bk, (float*)pk,
                                       Wv, bv, (float*)pv);

    cudaFuncSetAttribute(flash_tc_kernel, cudaFuncAttributeMaxDynamicSharedMemorySize,
                         FLASH_SMEM);
    flash_tc_kernel<<<dim3(S_LEN / 64, NH), 128, FLASH_SMEM>>>(
        (const float*)pq, (const float*)pk, (const float*)pv, (float*)pa);

    dim3 ggrid(D_MODEL / 128, S_LEN / 128);
    sgemm_bias_kernel<<<ggrid, 256>>>((const float*)pa, Wo, bo, (float*)pp,
                                      S_LEN, D_MODEL, D_MODEL);

    ln_kernel<<<S_LEN, 256>>>((const float*)ph, (const float*)pp, gamma, beta, out);
}

// round 14
// speedup vs baseline: 1.2207x; 1.2207x over previous
#include <cuda_runtime.h>
#include <math.h>

#define S_LEN 4096
#define D_MODEL 1024
#define NH 16
#define DHD 64

// ---- scratch (static device globals: allocation-free contract) ----
__device__ float g_h[S_LEN * D_MODEL];
__device__ float g_q[S_LEN * D_MODEL];
__device__ float g_k[S_LEN * D_MODEL];
__device__ float g_v[S_LEN * D_MODEL];
__device__ float g_att[S_LEN * D_MODEL];
__device__ float g_proj[S_LEN * D_MODEL];

// ---------------------------------------------------------------------------
// h = x + positional_encoding
// ---------------------------------------------------------------------------
__global__ void add_pe_kernel(const float* __restrict__ x, float* __restrict__ h) {
    int srow = blockIdx.x;
    int tid = threadIdx.x;
#pragma unroll
    for (int n = 0; n < 4; n++) {
        int d = tid + n * 256;
        float arg = (float)(d & ~1) * (-9.2103403719761836f / 1024.0f);  // -ln(10000)/D
        float dv = expf(arg);
        float a = (float)srow * dv;
        float pe = (d & 1) ? cosf(a) : sinf(a);
        int idx = srow * D_MODEL + d;
        h[idx] = x[idx] + pe;
    }
}

// ---------------------------------------------------------------------------
// tf32 helpers
// ---------------------------------------------------------------------------
__device__ __forceinline__ unsigned f2tf32(float x) {
    unsigned r;
    asm("cvt.rna.tf32.f32 %0, %1;" : "=r"(r) : "f"(x));
    return r;
}

__device__ __forceinline__ void mma_tf32(
    float& c0, float& c1, float& c2, float& c3,
    unsigned a0, unsigned a1, unsigned a2, unsigned a3,
    unsigned b0, unsigned b1) {
    asm("mma.sync.aligned.m16n8k8.row.col.f32.tf32.tf32.f32 "
        "{%0,%1,%2,%3}, {%4,%5,%6,%7}, {%8,%9}, {%0,%1,%2,%3};"
        : "+f"(c0), "+f"(c1), "+f"(c2), "+f"(c3)
        : "r"(a0), "r"(a1), "r"(a2), "r"(a3), "r"(b0), "r"(b1));
}

// ---------------------------------------------------------------------------
// 128x128x16 tf32 tensor-core GEMM body (validated R6), double-buffered.
// ---------------------------------------------------------------------------
#define KT 16
#define PITCH 136

__device__ __forceinline__ void sgemm_body(
    const float* __restrict__ A, const float* __restrict__ B,
    const float* __restrict__ bias, float* __restrict__ C,
    int M, int N, int K, int m0, int n0) {
    __shared__ unsigned As[2][KT][PITCH];
    __shared__ unsigned Bs[2][KT][PITCH];

    int tid = threadIdx.x;
    int wid = tid >> 5;
    int lane = tid & 31;
    int gid = lane >> 2;       // 0..7
    int tig = lane & 3;        // 0..3
    int wm = (wid & 3) * 32;   // warp row offset in tile
    int wn = (wid >> 2) * 64;  // warp col offset in tile

    int arow = tid >> 1;
    int acol = (tid & 1) * 4;
    int brow = tid >> 5;
    int bcol = (tid & 31) * 4;

    const float* Aptr = &A[(size_t)(m0 + arow) * K + acol];
    const float* Bptr = &B[(size_t)brow * N + n0 + bcol];

    float acc[2][8][4];
#pragma unroll
    for (int mt = 0; mt < 2; mt++)
#pragma unroll
        for (int nt = 0; nt < 8; nt++)
#pragma unroll
            for (int r = 0; r < 4; r++) acc[mt][nt][r] = 0.f;

    float4 a0p = *(const float4*)Aptr;
    float4 a1p = *(const float4*)(Aptr + 8);
    float4 b0p = *(const float4*)Bptr;
    float4 b1p = *(const float4*)(Bptr + (size_t)8 * N);
#pragma unroll
    for (int i = 0; i < 4; i++) {
        As[0][acol + i][arow]     = f2tf32(((const float*)&a0p)[i]);
        As[0][acol + 8 + i][arow] = f2tf32(((const float*)&a1p)[i]);
        Bs[0][brow][bcol + i]     = f2tf32(((const float*)&b0p)[i]);
        Bs[0][brow + 8][bcol + i] = f2tf32(((const float*)&b1p)[i]);
    }
    __syncthreads();

    int buf = 0;
    for (int k0 = 0; k0 < K; k0 += KT) {
        if (k0 + KT < K) {
            a0p = *(const float4*)(Aptr + k0 + KT);
            a1p = *(const float4*)(Aptr + k0 + KT + 8);
            b0p = *(const float4*)(Bptr + (size_t)(k0 + KT) * N);
            b1p = *(const float4*)(Bptr + (size_t)(k0 + KT + 8) * N);
        }

#pragma unroll
        for (int ks = 0; ks < KT; ks += 8) {
            unsigned af[2][4], bf[8][2];
#pragma unroll
            for (int mt = 0; mt < 2; mt++) {
                int r = wm + mt * 16 + gid;
                af[mt][0] = As[buf][ks + tig][r];
                af[mt][1] = As[buf][ks + tig][r + 8];
                af[mt][2] = As[buf][ks + tig + 4][r];
                af[mt][3] = As[buf][ks + tig + 4][r + 8];
            }
#pragma unroll
            for (int nt = 0; nt < 8; nt++) {
                int c = wn + nt * 8 + gid;
                bf[nt][0] = Bs[buf][ks + tig][c];
                bf[nt][1] = Bs[buf][ks + tig + 4][c];
            }
#pragma unroll
            for (int mt = 0; mt < 2; mt++)
#pragma unroll
                for (int nt = 0; nt < 8; nt++)
                    mma_tf32(acc[mt][nt][0], acc[mt][nt][1],
                             acc[mt][nt][2], acc[mt][nt][3],
                             af[mt][0], af[mt][1], af[mt][2], af[mt][3],
                             bf[nt][0], bf[nt][1]);
        }

        if (k0 + KT < K) {
            int nb = buf ^ 1;
#pragma unroll
            for (int i = 0; i < 4; i++) {
                As[nb][acol + i][arow]     = f2tf32(((const float*)&a0p)[i]);
                As[nb][acol + 8 + i][arow] = f2tf32(((const float*)&a1p)[i]);
                Bs[nb][brow][bcol + i]     = f2tf32(((const float*)&b0p)[i]);
                Bs[nb][brow + 8][bcol + i] = f2tf32(((const float*)&b1p)[i]);
            }
            __syncthreads();
            buf = nb;
        }
    }

#pragma unroll
    for (int mt = 0; mt < 2; mt++) {
#pragma unroll
        for (int nt = 0; nt < 8; nt++) {
            int row = m0 + wm + mt * 16 + gid;
            int col = n0 + wn + nt * 8 + tig * 2;
            float2 r0, r1;
            r0.x = acc[mt][nt][0] + bias[col];
            r0.y = acc[mt][nt][1] + bias[col + 1];
            r1.x = acc[mt][nt][2] + bias[col];
            r1.y = acc[mt][nt][3] + bias[col + 1];
            *(float2*)&C[(size_t)row * N + col]       = r0;
            *(float2*)&C[(size_t)(row + 8) * N + col] = r1;
        }
    }
}

__global__ __launch_bounds__(256, 2) void sgemm_bias_kernel(
    const float* __restrict__ A, const float* __restrict__ B,
    const float* __restrict__ bias, float* __restrict__ C,
    int M, int N, int K) {
    sgemm_body(A, B, bias, C, M, N, K, blockIdx.y * 128, blockIdx.x * 128);
}

__global__ __launch_bounds__(256, 2) void sgemm_qkv_kernel(
    const float* __restrict__ A,
    const float* __restrict__ Wq, const float* __restrict__ bq, float* __restrict__ q,
    const float* __restrict__ Wk, const float* __restrict__ bk, float* __restrict__ k,
    const float* __restrict__ Wv, const float* __restrict__ bv, float* __restrict__ v) {
    const float* B;
    const float* bias;
    float* C;
    if (blockIdx.z == 0)      { B = Wq; bias = bq; C = q; }
    else if (blockIdx.z == 1) { B = Wk; bias = bk; C = k; }
    else                      { B = Wv; bias = bv; C = v; }
    sgemm_body(A, B, bias, C, S_LEN, D_MODEL, D_MODEL,
               blockIdx.y * 128, blockIdx.x * 128);
}

// ---------------------------------------------------------------------------
// Flash attention with tf32 tensor cores — R8-validated structure (occ 4,
// direct gmem->smem tile loads, no register prefetch) + single change:
// Vs pitch 72 so PV B-loads hit banks 8*tig+gid (all 32 distinct).
// (Second submission attempt of this delta.)
// ---------------------------------------------------------------------------
#define FP 68
#define VP 72
#define FLASH_SMEM ((2 * 64 * FP + 64 * VP) * 4)

__global__ __launch_bounds__(128, 4) void flash_tc_kernel(
    const float* __restrict__ q, const float* __restrict__ k,
    const float* __restrict__ v, float* __restrict__ o_out) {
    extern __shared__ unsigned fsm[];
    unsigned* Ks = fsm;               // [key][dh]   64 x FP
    unsigned* Vs = fsm + 64 * FP;     // [key][dh]   64 x VP
    unsigned* Ps = Vs + 64 * VP;      // [qrow][key] 64 x FP

    int head = blockIdx.y;
    int qt = blockIdx.x;
    int tid = threadIdx.x;
    int wid = tid >> 5;
    int lane = tid & 31;
    int gid = lane >> 2;  // 0..7
    int tig = lane & 3;   // 0..3

    // preload Q A-fragments (x 1/8 scale), constant over all kt tiles
    unsigned aq[8][4];
    {
        const float* qb = q + (size_t)(qt * 64 + wid * 16) * D_MODEL + head * DHD;
#pragma unroll
        for (int ks = 0; ks < 8; ks++) {
            int c0 = ks * 8 + tig;
            aq[ks][0] = f2tf32(0.125f * qb[(size_t)gid * D_MODEL + c0]);
            aq[ks][1] = f2tf32(0.125f * qb[(size_t)(gid + 8) * D_MODEL + c0]);
            aq[ks][2] = f2tf32(0.125f * qb[(size_t)gid * D_MODEL + c0 + 4]);
            aq[ks][3] = f2tf32(0.125f * qb[(size_t)(gid + 8) * D_MODEL + c0 + 4]);
        }
    }

    float m0 = -INFINITY, m1 = -INFINITY, l0 = 0.f, l1 = 0.f;
    float o[8][4];
#pragma unroll
    for (int nt = 0; nt < 8; nt++)
#pragma unroll
        for (int r = 0; r < 4; r++) o[nt][r] = 0.f;

    int pr0 = wid * 16 + gid;       // this thread's P/O rows (warp-local tile)
    int pr1 = pr0 + 8;

    for (int kt = 0; kt < S_LEN / 64; kt++) {
        // ---- load K,V tile -> smem (tf32) ----
        const float* kb = k + (size_t)kt * 64 * D_MODEL + head * DHD;
        const float* vb = v + (size_t)kt * 64 * D_MODEL + head * DHD;
#pragma unroll
        for (int n = 0; n < 8; n++) {
            int f4 = n * 128 + tid;
            int key = f4 >> 4;
            int d4 = (f4 & 15) * 4;
            float4 kv4 = *(const float4*)&kb[(size_t)key * D_MODEL + d4];
            float4 vv4 = *(const float4*)&vb[(size_t)key * D_MODEL + d4];
            uint4 ku = {f2tf32(kv4.x), f2tf32(kv4.y), f2tf32(kv4.z), f2tf32(kv4.w)};
            uint4 vu = {f2tf32(vv4.x), f2tf32(vv4.y), f2tf32(vv4.z), f2tf32(vv4.w)};
            *(uint4*)&Ks[key * FP + d4] = ku;
            *(uint4*)&Vs[key * VP + d4] = vu;
        }
        __syncthreads();

        // ---- S = (Q/8) K^T  (pre-scaled) ----
        float s[8][4];
#pragma unroll
        for (int nt = 0; nt < 8; nt++)
#pragma unroll
            for (int r = 0; r < 4; r++) s[nt][r] = 0.f;

#pragma unroll
        for (int ks = 0; ks < 8; ks++) {
#pragma unroll
            for (int nt = 0; nt < 8; nt++) {
                int key = nt * 8 + gid;
                unsigned b0 = Ks[key * FP + ks * 8 + tig];
                unsigned b1 = Ks[key * FP + ks * 8 + tig + 4];
                mma_tf32(s[nt][0], s[nt][1], s[nt][2], s[nt][3],
                         aq[ks][0], aq[ks][1], aq[ks][2], aq[ks][3], b0, b1);
            }
        }

        // ---- online softmax (rows pr0=gid, pr1=gid+8 within warp tile) ----
        float mx0 = -INFINITY, mx1 = -INFINITY;
#pragma unroll
        for (int nt = 0; nt < 8; nt++) {
            mx0 = fmaxf(mx0, fmaxf(s[nt][0], s[nt][1]));
            mx1 = fmaxf(mx1, fmaxf(s[nt][2], s[nt][3]));
        }
        mx0 = fmaxf(mx0, __shfl_xor_sync(0xffffffffu, mx0, 1));
        mx0 = fmaxf(mx0, __shfl_xor_sync(0xffffffffu, mx0, 2));
        mx1 = fmaxf(mx1, __shfl_xor_sync(0xffffffffu, mx1, 1));
        mx1 = fmaxf(mx1, __shfl_xor_sync(0xffffffffu, mx1, 2));

        float mn0 = fmaxf(m0, mx0);
        float mn1 = fmaxf(m1, mx1);
        float c0 = __expf(m0 - mn0);
        float c1 = __expf(m1 - mn1);
        float rs0 = 0.f, rs1 = 0.f;
#pragma unroll
        for (int nt = 0; nt < 8; nt++) {
            s[nt][0] = __expf(s[nt][0] - mn0);
            s[nt][1] = __expf(s[nt][1] - mn0);
            s[nt][2] = __expf(s[nt][2] - mn1);
            s[nt][3] = __expf(s[nt][3] - mn1);
            rs0 += s[nt][0] + s[nt][1];
            rs1 += s[nt][2] + s[nt][3];
        }
        rs0 += __shfl_xor_sync(0xffffffffu, rs0, 1);
        rs0 += __shfl_xor_sync(0xffffffffu, rs0, 2);
        rs1 += __shfl_xor_sync(0xffffffffu, rs1, 1);
        rs1 += __shfl_xor_sync(0xffffffffu, rs1, 2);
        l0 = l0 * c0 + rs0;
        l1 = l1 * c1 + rs1;
        m0 = mn0;
        m1 = mn1;
#pragma unroll
        for (int nt = 0; nt < 8; nt++) {
            o[nt][0] *= c0;
            o[nt][1] *= c0;
            o[nt][2] *= c1;
            o[nt][3] *= c1;
        }

        // ---- P -> smem (tf32), warp-private rows ----
#pragma unroll
        for (int nt = 0; nt < 8; nt++) {
            int col = nt * 8 + tig * 2;
            uint2 p0 = {f2tf32(s[nt][0]), f2tf32(s[nt][1])};
            uint2 p1 = {f2tf32(s[nt][2]), f2tf32(s[nt][3])};
            *(uint2*)&Ps[pr0 * FP + col] = p0;
            *(uint2*)&Ps[pr1 * FP + col] = p1;
        }
        __syncwarp();

        // ---- O += P V ----
#pragma unroll
        for (int ks = 0; ks < 8; ks++) {
            unsigned ap0 = Ps[pr0 * FP + ks * 8 + tig];
            unsigned ap1 = Ps[pr1 * FP + ks * 8 + tig];
            unsigned ap2 = Ps[pr0 * FP + ks * 8 + tig + 4];
            unsigned ap3 = Ps[pr1 * FP + ks * 8 + tig + 4];
#pragma unroll
            for (int nt = 0; nt < 8; nt++) {
                unsigned b0 = Vs[(ks * 8 + tig) * VP + nt * 8 + gid];
                unsigned b1 = Vs[(ks * 8 + tig + 4) * VP + nt * 8 + gid];
                mma_tf32(o[nt][0], o[nt][1], o[nt][2], o[nt][3],
                         ap0, ap1, ap2, ap3, b0, b1);
            }
        }
        __syncthreads();  // Ks/Vs reused next tile
    }

    // ---- epilogue: O / l ----
    float inv0 = 1.0f / l0;
    float inv1 = 1.0f / l1;
    float* ob = o_out + (size_t)(qt * 64 + wid * 16) * D_MODEL + head * DHD;
#pragma unroll
    for (int nt = 0; nt < 8; nt++) {
        int col = nt * 8 + tig * 2;
        float2 r0 = {o[nt][0] * inv0, o[nt][1] * inv0};
        float2 r1 = {o[nt][2] * inv1, o[nt][3] * inv1};
        *(float2*)&ob[(size_t)gid * D_MODEL + col]       = r0;
        *(float2*)&ob[(size_t)(gid + 8) * D_MODEL + col] = r1;
    }
}

// ---------------------------------------------------------------------------
// y = LN(h + proj) * gamma + beta   (one block per row)
// ---------------------------------------------------------------------------
__global__ __launch_bounds__(256) void ln_kernel(
    const float* __restrict__ h, const float* __restrict__ p,
    const float* __restrict__ gamma, const float* __restrict__ beta,
    float* __restrict__ out) {
    int row = blockIdx.x;
    int tid = threadIdx.x;
    float v[4];
    float s = 0.f, s2 = 0.f;
#pragma unroll
    for (int n = 0; n < 4; n++) {
        int c = tid + n * 256;
        float val = h[(size_t)row * D_MODEL + c] + p[(size_t)row * D_MODEL + c];
        v[n] = val;
        s += val;
        s2 += val * val;
    }
#pragma unroll
    for (int off = 16; off >= 1; off >>= 1) {
        s += __shfl_xor_sync(0xffffffffu, s, off);
        s2 += __shfl_xor_sync(0xffffffffu, s2, off);
    }
    __shared__ float sb[8], sb2[8];
    int w = tid >> 5, lane = tid & 31;
    if (lane == 0) { sb[w] = s; sb2[w] = s2; }
    __syncthreads();
    if (tid == 0) {
        float a = 0.f, b = 0.f;
        for (int i = 0; i < 8; i++) { a += sb[i]; b += sb2[i]; }
        sb[0] = a; sb2[0] = b;
    }
    __syncthreads();
    float mean = sb[0] * (1.0f / 1024.0f);
    float var = sb2[0] * (1.0f / 1024.0f) - mean * mean;
    float inv = rsqrtf(var + 1e-5f);
#pragma unroll
    for (int n = 0; n < 4; n++) {
        int c = tid + n * 256;
        out[(size_t)row * D_MODEL + c] = (v[n] - mean) * inv * gamma[c] + beta[c];
    }
}

// ---------------------------------------------------------------------------
extern "C" void kernel_launch(void* const* d_in, const int* in_sizes, int n_in,
                              void* d_out, int out_size) {
    const float* x  = (const float*)d_in[0];
    const float* Wq = (const float*)d_in[1];
    const float* bq = (const float*)d_in[2];
    const float* Wk = (const float*)d_in[3];
    const float* bk = (const float*)d_in[4];
    const float* Wv = (const float*)d_in[5];
    const float* bv = (const float*)d_in[6];
    const float* Wo = (const float*)d_in[7];
    const float* bo = (const float*)d_in[8];
    const float* gamma = (const float*)d_in[9];
    const float* beta  = (const float*)d_in[10];
    float* out = (float*)d_out;

    void *ph, *pq, *pk, *pv, *pa, *pp;
    cudaGetSymbolAddress(&ph, g_h);
    cudaGetSymbolAddress(&pq, g_q);
    cudaGetSymbolAddress(&pk, g_k);
    cudaGetSymbolAddress(&pv, g_v);
    cudaGetSymbolAddress(&pa, g_att);
    cudaGetSymbolAddress(&pp, g_proj);

    add_pe_kernel<<<S_LEN, 256>>>(x, (float*)ph);

    dim3 qkvgrid(D_MODEL / 128, S_LEN / 128, 3);
    sgemm_qkv_kernel<<<qkvgrid, 256>>>((const float*)ph,
                                       Wq, bq, (float*)pq,
                                       Wk, bk, (float*)pk,
                                       Wv, bv, (float*)pv);

    cudaFuncSetAttribute(flash_tc_kernel, cudaFuncAttributeMaxDynamicSharedMemorySize,
                         FLASH_SMEM);
    flash_tc_kernel<<<dim3(S_LEN / 64, NH), 128, FLASH_SMEM>>>(
        (const float*)pq, (const float*)pk, (const float*)pv, (float*)pa);

    dim3 ggrid(D_MODEL / 128, S_LEN / 128);
    sgemm_bias_kernel<<<ggrid, 256>>>((const float*)pa, Wo, bo, (float*)pp,
                                      S_LEN, D_MODEL, D_MODEL);

    ln_kernel<<<S_LEN, 256>>>((const float*)ph, (const float*)pp, gamma, beta, out);
}

// round 17
// speedup vs baseline: 1.2880x; 1.0552x over previous
#include <cuda_runtime.h>
#include <math.h>

#define S_LEN 4096
#define D_MODEL 1024
#define NH 16
#define DHD 64

// ---- scratch (static device globals: allocation-free contract) ----
__device__ float g_h[S_LEN * D_MODEL];
__device__ float g_q[S_LEN * D_MODEL];
__device__ float g_k[S_LEN * D_MODEL];
__device__ float g_v[S_LEN * D_MODEL];
__device__ float g_att[S_LEN * D_MODEL];
__device__ float g_proj[S_LEN * D_MODEL];

// ---------------------------------------------------------------------------
// h = x + positional_encoding
// ---------------------------------------------------------------------------
__global__ void add_pe_kernel(const float* __restrict__ x, float* __restrict__ h) {
    int srow = blockIdx.x;
    int tid = threadIdx.x;
#pragma unroll
    for (int n = 0; n < 4; n++) {
        int d = tid + n * 256;
        float arg = (float)(d & ~1) * (-9.2103403719761836f / 1024.0f);  // -ln(10000)/D
        float dv = expf(arg);
        float a = (float)srow * dv;
        float pe = (d & 1) ? cosf(a) : sinf(a);
        int idx = srow * D_MODEL + d;
        h[idx] = x[idx] + pe;
    }
}

// ---------------------------------------------------------------------------
// tf32 helpers
// ---------------------------------------------------------------------------
__device__ __forceinline__ unsigned f2tf32(float x) {
    unsigned r;
    asm("cvt.rna.tf32.f32 %0, %1;" : "=r"(r) : "f"(x));
    return r;
}

__device__ __forceinline__ void mma_tf32(
    float& c0, float& c1, float& c2, float& c3,
    unsigned a0, unsigned a1, unsigned a2, unsigned a3,
    unsigned b0, unsigned b1) {
    asm("mma.sync.aligned.m16n8k8.row.col.f32.tf32.tf32.f32 "
        "{%0,%1,%2,%3}, {%4,%5,%6,%7}, {%8,%9}, {%0,%1,%2,%3};"
        : "+f"(c0), "+f"(c1), "+f"(c2), "+f"(c3)
        : "r"(a0), "r"(a1), "r"(a2), "r"(a3), "r"(b0), "r"(b1));
}

// ---------------------------------------------------------------------------
// 128x128x16 tf32 tensor-core GEMM, double-buffered.
// R16 (second submission attempt): 128 threads / 4 warps, each warp owns a
// 64x64 tile (mt=4, nt=8). Smem layouts, fragment formulas and bank patterns
// identical to the R14-validated version; each thread performs the fill work
// of two old threads (t and t+128). Arithmetic per output unchanged.
// ---------------------------------------------------------------------------
#define KT 16
#define PITCH 136

__device__ __forceinline__ void sgemm_body(
    const float* __restrict__ A, const float* __restrict__ B,
    const float* __restrict__ bias, float* __restrict__ C,
    int M, int N, int K, int m0, int n0) {
    __shared__ unsigned As[2][KT][PITCH];
    __shared__ unsigned Bs[2][KT][PITCH];

    int tid = threadIdx.x;      // 0..127
    int wid = tid >> 5;         // 0..3
    int lane = tid & 31;
    int gid = lane >> 2;        // 0..7
    int tig = lane & 3;         // 0..3
    int wm = (wid & 1) * 64;    // warp row offset
    int wn = (wid >> 1) * 64;   // warp col offset

    // gmem fill mapping: this thread does old threads t0=tid and t1=tid+128
    int arow0 = tid >> 1;            // 0..63
    int acol  = (tid & 1) * 4;       // 0 or 4
    int arow1 = arow0 + 64;          // 64..127
    int brow0 = tid >> 5;            // 0..3
    int bcol  = (tid & 31) * 4;      // 0..124
    int brow1 = brow0 + 4;           // 4..7

    const float* Aptr0 = &A[(size_t)(m0 + arow0) * K + acol];
    const float* Aptr1 = &A[(size_t)(m0 + arow1) * K + acol];
    const float* Bptr0 = &B[(size_t)brow0 * N + n0 + bcol];
    const float* Bptr1 = &B[(size_t)brow1 * N + n0 + bcol];

    float acc[4][8][4];
#pragma unroll
    for (int mt = 0; mt < 4; mt++)
#pragma unroll
        for (int nt = 0; nt < 8; nt++)
#pragma unroll
            for (int r = 0; r < 4; r++) acc[mt][nt][r] = 0.f;

    // prologue: tile 0 -> buffer 0
    float4 a00 = *(const float4*)Aptr0;
    float4 a01 = *(const float4*)(Aptr0 + 8);
    float4 a10 = *(const float4*)Aptr1;
    float4 a11 = *(const float4*)(Aptr1 + 8);
    float4 b00 = *(const float4*)Bptr0;
    float4 b01 = *(const float4*)(Bptr0 + (size_t)8 * N);
    float4 b10 = *(const float4*)Bptr1;
    float4 b11 = *(const float4*)(Bptr1 + (size_t)8 * N);
#pragma unroll
    for (int i = 0; i < 4; i++) {
        As[0][acol + i][arow0]     = f2tf32(((const float*)&a00)[i]);
        As[0][acol + 8 + i][arow0] = f2tf32(((const float*)&a01)[i]);
        As[0][acol + i][arow1]     = f2tf32(((const float*)&a10)[i]);
        As[0][acol + 8 + i][arow1] = f2tf32(((const float*)&a11)[i]);
        Bs[0][brow0][bcol + i]     = f2tf32(((const float*)&b00)[i]);
        Bs[0][brow0 + 8][bcol + i] = f2tf32(((const float*)&b01)[i]);
        Bs[0][brow1][bcol + i]     = f2tf32(((const float*)&b10)[i]);
        Bs[0][brow1 + 8][bcol + i] = f2tf32(((const float*)&b11)[i]);
    }
    __syncthreads();

    int buf = 0;
    for (int k0 = 0; k0 < K; k0 += KT) {
        if (k0 + KT < K) {
            a00 = *(const float4*)(Aptr0 + k0 + KT);
            a01 = *(const float4*)(Aptr0 + k0 + KT + 8);
            a10 = *(const float4*)(Aptr1 + k0 + KT);
            a11 = *(const float4*)(Aptr1 + k0 + KT + 8);
            b00 = *(const float4*)(Bptr0 + (size_t)(k0 + KT) * N);
            b01 = *(const float4*)(Bptr0 + (size_t)(k0 + KT + 8) * N);
            b10 = *(const float4*)(Bptr1 + (size_t)(k0 + KT) * N);
            b11 = *(const float4*)(Bptr1 + (size_t)(k0 + KT + 8) * N);
        }

#pragma unroll
        for (int ks = 0; ks < KT; ks += 8) {
            unsigned af[4][4], bf[8][2];
#pragma unroll
            for (int mt = 0; mt < 4; mt++) {
                int r = wm + mt * 16 + gid;
                af[mt][0] = As[buf][ks + tig][r];
                af[mt][1] = As[buf][ks + tig][r + 8];
                af[mt][2] = As[buf][ks + tig + 4][r];
                af[mt][3] = As[buf][ks + tig + 4][r + 8];
            }
#pragma unroll
            for (int nt = 0; nt < 8; nt++) {
                int c = wn + nt * 8 + gid;
                bf[nt][0] = Bs[buf][ks + tig][c];
                bf[nt][1] = Bs[buf][ks + tig + 4][c];
            }
#pragma unroll
            for (int mt = 0; mt < 4; mt++)
#pragma unroll
                for (int nt = 0; nt < 8; nt++)
                    mma_tf32(acc[mt][nt][0], acc[mt][nt][1],
                             acc[mt][nt][2], acc[mt][nt][3],
                             af[mt][0], af[mt][1], af[mt][2], af[mt][3],
                             bf[nt][0], bf[nt][1]);
        }

        if (k0 + KT < K) {
            int nb = buf ^ 1;
#pragma unroll
            for (int i = 0; i < 4; i++) {
                As[nb][acol + i][arow0]     = f2tf32(((const float*)&a00)[i]);
                As[nb][acol + 8 + i][arow0] = f2tf32(((const float*)&a01)[i]);
                As[nb][acol + i][arow1]     = f2tf32(((const float*)&a10)[i]);
                As[nb][acol + 8 + i][arow1] = f2tf32(((const float*)&a11)[i]);
                Bs[nb][brow0][bcol + i]     = f2tf32(((const float*)&b00)[i]);
                Bs[nb][brow0 + 8][bcol + i] = f2tf32(((const float*)&b01)[i]);
                Bs[nb][brow1][bcol + i]     = f2tf32(((const float*)&b10)[i]);
                Bs[nb][brow1 + 8][bcol + i] = f2tf32(((const float*)&b11)[i]);
            }
            __syncthreads();
            buf = nb;
        }
    }

#pragma unroll
    for (int mt = 0; mt < 4; mt++) {
#pragma unroll
        for (int nt = 0; nt < 8; nt++) {
            int row = m0 + wm + mt * 16 + gid;
            int col = n0 + wn + nt * 8 + tig * 2;
            float2 r0, r1;
            r0.x = acc[mt][nt][0] + bias[col];
            r0.y = acc[mt][nt][1] + bias[col + 1];
            r1.x = acc[mt][nt][2] + bias[col];
            r1.y = acc[mt][nt][3] + bias[col + 1];
            *(float2*)&C[(size_t)row * N + col]       = r0;
            *(float2*)&C[(size_t)(row + 8) * N + col] = r1;
        }
    }
}

__global__ __launch_bounds__(128, 2) void sgemm_bias_kernel(
    const float* __restrict__ A, const float* __restrict__ B,
    const float* __restrict__ bias, float* __restrict__ C,
    int M, int N, int K) {
    sgemm_body(A, B, bias, C, M, N, K, blockIdx.y * 128, blockIdx.x * 128);
}

__global__ __launch_bounds__(128, 2) void sgemm_qkv_kernel(
    const float* __restrict__ A,
    const float* __restrict__ Wq, const float* __restrict__ bq, float* __restrict__ q,
    const float* __restrict__ Wk, const float* __restrict__ bk, float* __restrict__ k,
    const float* __restrict__ Wv, const float* __restrict__ bv, float* __restrict__ v) {
    const float* B;
    const float* bias;
    float* C;
    if (blockIdx.z == 0)      { B = Wq; bias = bq; C = q; }
    else if (blockIdx.z == 1) { B = Wk; bias = bk; C = k; }
    else                      { B = Wv; bias = bv; C = v; }
    sgemm_body(A, B, bias, C, S_LEN, D_MODEL, D_MODEL,
               blockIdx.y * 128, blockIdx.x * 128);
}

// ---------------------------------------------------------------------------
// Flash attention with tf32 tensor cores — R14-validated (962 us): occ 4,
// direct gmem->smem tile loads, Vs pitch 72 (conflict-free PV B-loads).
// FROZEN.
// ---------------------------------------------------------------------------
#define FP 68
#define VP 72
#define FLASH_SMEM ((2 * 64 * FP + 64 * VP) * 4)

__global__ __launch_bounds__(128, 4) void flash_tc_kernel(
    const float* __restrict__ q, const float* __restrict__ k,
    const float* __restrict__ v, float* __restrict__ o_out) {
    extern __shared__ unsigned fsm[];
    unsigned* Ks = fsm;               // [key][dh]   64 x FP
    unsigned* Vs = fsm + 64 * FP;     // [key][dh]   64 x VP
    unsigned* Ps = Vs + 64 * VP;      // [qrow][key] 64 x FP

    int head = blockIdx.y;
    int qt = blockIdx.x;
    int tid = threadIdx.x;
    int wid = tid >> 5;
    int lane = tid & 31;
    int gid = lane >> 2;  // 0..7
    int tig = lane & 3;   // 0..3

    // preload Q A-fragments (x 1/8 scale), constant over all kt tiles
    unsigned aq[8][4];
    {
        const float* qb = q + (size_t)(qt * 64 + wid * 16) * D_MODEL + head * DHD;
#pragma unroll
        for (int ks = 0; ks < 8; ks++) {
            int c0 = ks * 8 + tig;
            aq[ks][0] = f2tf32(0.125f * qb[(size_t)gid * D_MODEL + c0]);
            aq[ks][1] = f2tf32(0.125f * qb[(size_t)(gid + 8) * D_MODEL + c0]);
            aq[ks][2] = f2tf32(0.125f * qb[(size_t)gid * D_MODEL + c0 + 4]);
            aq[ks][3] = f2tf32(0.125f * qb[(size_t)(gid + 8) * D_MODEL + c0 + 4]);
        }
    }

    float m0 = -INFINITY, m1 = -INFINITY, l0 = 0.f, l1 = 0.f;
    float o[8][4];
#pragma unroll
    for (int nt = 0; nt < 8; nt++)
#pragma unroll
        for (int r = 0; r < 4; r++) o[nt][r] = 0.f;

    int pr0 = wid * 16 + gid;       // this thread's P/O rows (warp-local tile)
    int pr1 = pr0 + 8;

    for (int kt = 0; kt < S_LEN / 64; kt++) {
        // ---- load K,V tile -> smem (tf32) ----
        const float* kb = k + (size_t)kt * 64 * D_MODEL + head * DHD;
        const float* vb = v + (size_t)kt * 64 * D_MODEL + head * DHD;
#pragma unroll
        for (int n = 0; n < 8; n++) {
            int f4 = n * 128 + tid;
            int key = f4 >> 4;
            int d4 = (f4 & 15) * 4;
            float4 kv4 = *(const float4*)&kb[(size_t)key * D_MODEL + d4];
            float4 vv4 = *(const float4*)&vb[(size_t)key * D_MODEL + d4];
            uint4 ku = {f2tf32(kv4.x), f2tf32(kv4.y), f2tf32(kv4.z), f2tf32(kv4.w)};
            uint4 vu = {f2tf32(vv4.x), f2tf32(vv4.y), f2tf32(vv4.z), f2tf32(vv4.w)};
            *(uint4*)&Ks[key * FP + d4] = ku;
            *(uint4*)&Vs[key * VP + d4] = vu;
        }
        __syncthreads();

        // ---- S = (Q/8) K^T  (pre-scaled) ----
        float s[8][4];
#pragma unroll
        for (int nt = 0; nt < 8; nt++)
#pragma unroll
            for (int r = 0; r < 4; r++) s[nt][r] = 0.f;

#pragma unroll
        for (int ks = 0; ks < 8; ks++) {
#pragma unroll
            for (int nt = 0; nt < 8; nt++) {
                int key = nt * 8 + gid;
                unsigned b0 = Ks[key * FP + ks * 8 + tig];
                unsigned b1 = Ks[key * FP + ks * 8 + tig + 4];
                mma_tf32(s[nt][0], s[nt][1], s[nt][2], s[nt][3],
                         aq[ks][0], aq[ks][1], aq[ks][2], aq[ks][3], b0, b1);
            }
        }

        // ---- online softmax (rows pr0=gid, pr1=gid+8 within warp tile) ----
        float mx0 = -INFINITY, mx1 = -INFINITY;
#pragma unroll
        for (int nt = 0; nt < 8; nt++) {
            mx0 = fmaxf(mx0, fmaxf(s[nt][0], s[nt][1]));
            mx1 = fmaxf(mx1, fmaxf(s[nt][2], s[nt][3]));
        }
        mx0 = fmaxf(mx0, __shfl_xor_sync(0xffffffffu, mx0, 1));
        mx0 = fmaxf(mx0, __shfl_xor_sync(0xffffffffu, mx0, 2));
        mx1 = fmaxf(mx1, __shfl_xor_sync(0xffffffffu, mx1, 1));
        mx1 = fmaxf(mx1, __shfl_xor_sync(0xffffffffu, mx1, 2));

        float mn0 = fmaxf(m0, mx0);
        float mn1 = fmaxf(m1, mx1);
        float c0 = __expf(m0 - mn0);
        float c1 = __expf(m1 - mn1);
        float rs0 = 0.f, rs1 = 0.f;
#pragma unroll
        for (int nt = 0; nt < 8; nt++) {
            s[nt][0] = __expf(s[nt][0] - mn0);
            s[nt][1] = __expf(s[nt][1] - mn0);
            s[nt][2] = __expf(s[nt][2] - mn1);
            s[nt][3] = __expf(s[nt][3] - mn1);
            rs0 += s[nt][0] + s[nt][1];
            rs1 += s[nt][2] + s[nt][3];
        }
        rs0 += __shfl_xor_sync(0xffffffffu, rs0, 1);
        rs0 += __shfl_xor_sync(0xffffffffu, rs0, 2);
        rs1 += __shfl_xor_sync(0xffffffffu, rs1, 1);
        rs1 += __shfl_xor_sync(0xffffffffu, rs1, 2);
        l0 = l0 * c0 + rs0;
        l1 = l1 * c1 + rs1;
        m0 = mn0;
        m1 = mn1;
#pragma unroll
        for (int nt = 0; nt < 8; nt++) {
            o[nt][0] *= c0;
            o[nt][1] *= c0;
            o[nt][2] *= c1;
            o[nt][3] *= c1;
        }

        // ---- P -> smem (tf32), warp-private rows ----
#pragma unroll
        for (int nt = 0; nt < 8; nt++) {
            int col = nt * 8 + tig * 2;
            uint2 p0 = {f2tf32(s[nt][0]), f2tf32(s[nt][1])};
            uint2 p1 = {f2tf32(s[nt][2]), f2tf32(s[nt][3])};
            *(uint2*)&Ps[pr0 * FP + col] = p0;
            *(uint2*)&Ps[pr1 * FP + col] = p1;
        }
        __syncwarp();

        // ---- O += P V ----
#pragma unroll
        for (int ks = 0; ks < 8; ks++) {
            unsigned ap0 = Ps[pr0 * FP + ks * 8 + tig];
            unsigned ap1 = Ps[pr1 * FP + ks * 8 + tig];
            unsigned ap2 = Ps[pr0 * FP + ks * 8 + tig + 4];
            unsigned ap3 = Ps[pr1 * FP + ks * 8 + tig + 4];
#pragma unroll
            for (int nt = 0; nt < 8; nt++) {
                unsigned b0 = Vs[(ks * 8 + tig) * VP + nt * 8 + gid];
                unsigned b1 = Vs[(ks * 8 + tig + 4) * VP + nt * 8 + gid];
                mma_tf32(o[nt][0], o[nt][1], o[nt][2], o[nt][3],
                         ap0, ap1, ap2, ap3, b0, b1);
            }
        }
        __syncthreads();  // Ks/Vs reused next tile
    }

    // ---- epilogue: O / l ----
    float inv0 = 1.0f / l0;
    float inv1 = 1.0f / l1;
    float* ob = o_out + (size_t)(qt * 64 + wid * 16) * D_MODEL + head * DHD;
#pragma unroll
    for (int nt = 0; nt < 8; nt++) {
        int col = nt * 8 + tig * 2;
        float2 r0 = {o[nt][0] * inv0, o[nt][1] * inv0};
        float2 r1 = {o[nt][2] * inv1, o[nt][3] * inv1};
        *(float2*)&ob[(size_t)gid * D_MODEL + col]       = r0;
        *(float2*)&ob[(size_t)(gid + 8) * D_MODEL + col] = r1;
    }
}

// ---------------------------------------------------------------------------
// y = LN(h + proj) * gamma + beta   (one block per row)
// ---------------------------------------------------------------------------
__global__ __launch_bounds__(256) void ln_kernel(
    const float* __restrict__ h, const float* __restrict__ p,
    const float* __restrict__ gamma, const float* __restrict__ beta,
    float* __restrict__ out) {
    int row = blockIdx.x;
    int tid = threadIdx.x;
    float v[4];
    float s = 0.f, s2 = 0.f;
#pragma unroll
    for (int n = 0; n < 4; n++) {
        int c = tid + n * 256;
        float val = h[(size_t)row * D_MODEL + c] + p[(size_t)row * D_MODEL + c];
        v[n] = val;
        s += val;
        s2 += val * val;
    }
#pragma unroll
    for (int off = 16; off >= 1; off >>= 1) {
        s += __shfl_xor_sync(0xffffffffu, s, off);
        s2 += __shfl_xor_sync(0xffffffffu, s2, off);
    }
    __shared__ float sb[8], sb2[8];
    int w = tid >> 5, lane = tid & 31;
    if (lane == 0) { sb[w] = s; sb2[w] = s2; }
    __syncthreads();
    if (tid == 0) {
        float a = 0.f, b = 0.f;
        for (int i = 0; i < 8; i++) { a += sb[i]; b += sb2[i]; }
        sb[0] = a; sb2[0] = b;
    }
    __syncthreads();
    float mean = sb[0] * (1.0f / 1024.0f);
    float var = sb2[0] * (1.0f / 1024.0f) - mean * mean;
    float inv = rsqrtf(var + 1e-5f);
#pragma unroll
    for (int n = 0; n < 4; n++) {
        int c = tid + n * 256;
        out[(size_t)row * D_MODEL + c] = (v[n] - mean) * inv * gamma[c] + beta[c];
    }
}

// ---------------------------------------------------------------------------
extern "C" void kernel_launch(void* const* d_in, const int* in_sizes, int n_in,
                              void* d_out, int out_size) {
    const float* x  = (const float*)d_in[0];
    const float* Wq = (const float*)d_in[1];
    const float* bq = (const float*)d_in[2];
    const float* Wk = (const float*)d_in[3];
    const float* bk = (const float*)d_in[4];
    const float* Wv = (const float*)d_in[5];
    const float* bv = (const float*)d_in[6];
    const float* Wo = (const float*)d_in[7];
    const float* bo = (const float*)d_in[8];
    const float* gamma = (const float*)d_in[9];
    const float* beta  = (const float*)d_in[10];
    float* out = (float*)d_out;

    void *ph, *pq, *pk, *pv, *pa, *pp;
    cudaGetSymbolAddress(&ph, g_h);
    cudaGetSymbolAddress(&pq, g_q);
    cudaGetSymbolAddress(&pk, g_k);
    cudaGetSymbolAddress(&pv, g_v);
    cudaGetSymbolAddress(&pa, g_att);
    cudaGetSymbolAddress(&pp, g_proj);

    add_pe_kernel<<<S_LEN, 256>>>(x, (float*)ph);

    dim3 qkvgrid(D_MODEL / 128, S_LEN / 128, 3);
    sgemm_qkv_kernel<<<qkvgrid, 128>>>((const float*)ph,
                                       Wq, bq, (float*)pq,
                                       Wk, bk, (float*)pk,
                                       Wv, bv, (float*)pv);

    cudaFuncSetAttribute(flash_tc_kernel, cudaFuncAttributeMaxDynamicSharedMemorySize,
                         FLASH_SMEM);
    flash_tc_kernel<<<dim3(S_LEN / 64, NH), 128, FLASH_SMEM>>>(
        (const float*)pq, (const float*)pk, (const float*)pv, (float*)pa);

    dim3 ggrid(D_MODEL / 128, S_LEN / 128);
    sgemm_bias_kernel<<<ggrid, 128>>>((const float*)pa, Wo, bo, (float*)pp,
                                      S_LEN, D_MODEL, D_MODEL);

    ln_kernel<<<S_LEN, 256>>>((const float*)ph, (const float*)pp, gamma, beta, out);
}